// round 9
// baseline (speedup 1.0000x reference)
#include <cuda_runtime.h>
#include <cstdint>
#include <math.h>

#define BATCH 8192
#define NORB  128
#define NFER  32
#define HID   512
#define NOS   256          // orbital-sectors: 2 spin sectors * 128 orbitals
#define MTILE 256          // rows per k_gemm CTA (static smem, no attribute call)
#define YTILES 12          // covers bucket counts up to 3072 (mean 2048, sigma 39)

// ---------------- scratch (static device globals; no runtime allocation) ----
__device__ float    g_h[BATCH * HID];            // hidden activations (tf32-rounded)
__device__ unsigned g_mask[BATCH * 8];           // 256-bit occupancy bitmask per sample
__device__ int      g_cnt[NOS];                  // bucket counts
__device__ int      g_list[NOS * BATCH];         // bucket entries: (b<<5)|slot
__device__ float    g_A[2 * BATCH * NFER * NFER];// gathered backflow matrices

__device__ __forceinline__ unsigned f2tf32(float f) {
    unsigned u;
    asm("cvt.rna.tf32.f32 %0, %1;" : "=r"(u) : "f"(f));
    return u;
}
__device__ __forceinline__ unsigned fu(float f) { return __float_as_uint(f); }

__device__ __forceinline__ void mma_tf32(float c[4],
                                         unsigned a0, unsigned a1,
                                         unsigned a2, unsigned a3,
                                         unsigned b0, unsigned b1) {
    asm volatile(
        "mma.sync.aligned.m16n8k8.row.col.f32.tf32.tf32.f32 "
        "{%0,%1,%2,%3}, {%4,%5,%6,%7}, {%8,%9}, {%0,%1,%2,%3};"
        : "+f"(c[0]), "+f"(c[1]), "+f"(c[2]), "+f"(c[3])
        : "r"(a0), "r"(a1), "r"(a2), "r"(a3), "r"(b0), "r"(b1));
}

// ---------------- K0: zero bucket counters (must rerun every replay) --------
__global__ void k_zero() {
    if (threadIdx.x < NOS) g_cnt[threadIdx.x] = 0;
}

// ---------------- K1: occupancy scan, bitmasks, bucket build ----------------
__global__ void k_index(const int* __restrict__ n) {
    int gw   = (blockIdx.x * blockDim.x + threadIdx.x) >> 5;
    int lane = threadIdx.x & 31;
    int b    = gw;
    int cnt  = 0;
    #pragma unroll
    for (int c = 0; c < 8; c++) {
        if (c == 4) cnt = 0;             // sector boundary (k = 128)
        int v = n[b * 256 + c * 32 + lane];
        unsigned msk = __ballot_sync(0xffffffffu, v != 0);
        if (lane == 0) g_mask[b * 8 + c] = msk;
        int slot = cnt + __popc(msk & ((1u << lane) - 1u));
        cnt += __popc(msk);
        if (v) {
            int os  = ((c >> 2) << 7) | ((c & 3) << 5) | lane;
            int pos = atomicAdd(&g_cnt[os], 1);
            g_list[os * BATCH + pos] = (b << 5) | slot;
        }
    }
}

// ---------------- K2: h = tanh(b1 + sum of occupied W1 rows) ----------------
__global__ void __launch_bounds__(512) k_hidden(const float* __restrict__ W1,
                                                const float* __restrict__ b1) {
    __shared__ __align__(16) float tile[16 * 512];
    int tid  = threadIdx.x;
    int lane = tid & 31;
    int wsam = tid >> 5;
    int b    = blockIdx.x * 16 + wsam;

    float4 acc[4];
    #pragma unroll
    for (int i = 0; i < 4; i++) acc[i] = ((const float4*)b1)[i * 32 + lane];

    for (int t = 0; t < 16; t++) {
        int k0 = t * 16;
        __syncthreads();
        #pragma unroll
        for (int q = 0; q < 4; q++) {
            int ig = q * 512 + tid;
            ((float4*)tile)[ig] = ((const float4*)W1)[k0 * 128 + ig];
        }
        __syncthreads();
        unsigned bits = (g_mask[b * 8 + (t >> 1)] >> ((t & 1) * 16)) & 0xFFFFu;
        while (bits) {
            int kk = __ffs(bits) - 1; bits &= bits - 1;
            const float4* row = (const float4*)(tile + kk * 512);
            #pragma unroll
            for (int i = 0; i < 4; i++) {
                float4 v = row[i * 32 + lane];
                acc[i].x += v.x; acc[i].y += v.y; acc[i].z += v.z; acc[i].w += v.w;
            }
        }
    }
    float4* ho = (float4*)(g_h + b * HID);
    #pragma unroll
    for (int i = 0; i < 4; i++) {
        float4 v = acc[i];
        v.x = __uint_as_float(f2tf32(tanhf(v.x)));
        v.y = __uint_as_float(f2tf32(tanhf(v.y)));
        v.z = __uint_as_float(f2tf32(tanhf(v.z)));
        v.w = __uint_as_float(f2tf32(tanhf(v.w)));
        ho[i * 32 + lane] = v;
    }
}

// ---------------- K3: grouped masked GEMM (tf32 mma.sync, 256m tiles) -------
// Paired-float2 XOR-swizzled layout: logical 8B slot jl = ks*4+tg of row m is
// stored at jp = jl ^ ((m&7)<<1). Fragment pairs (a0,a2)/(a1,a3)/(b0,b1) load
// as one conflict-minimal LDS.64; staging STS.128 is conflict-minimal.
__device__ __forceinline__ void stage_row(float2* dst16, const float* src, int m) {
    int key23 = (m >> 1) & 3, key1 = m & 1;
    #pragma unroll
    for (int ks = 0; ks < 4; ks++) {
        float4 va = *(const float4*)(src + ks * 8);
        float4 vb = *(const float4*)(src + ks * 8 + 4);
        float2* dst = dst16 + ((ks ^ key23) << 2);
        float4 p01 = make_float4(va.x, vb.x, va.y, vb.y);
        float4 p23 = make_float4(va.z, vb.z, va.w, vb.w);
        *(float4*)dst       = key1 ? p23 : p01;
        *(float4*)(dst + 2) = key1 ? p01 : p23;
    }
}

__global__ void __launch_bounds__(256)
k_gemm(const float* __restrict__ W2, const float* __restrict__ b2,
       const float* __restrict__ M1, const float* __restrict__ M2) {
    __shared__ __align__(16) float2 ht2[MTILE][16];   // 32 KB
    __shared__ __align__(16) float2 bt2[32][16];      //  4 KB
    __shared__ int   ents[MTILE];
    __shared__ float madd[32];

    int os = blockIdx.x;
    int mo = blockIdx.y * MTILE;
    int cnt = g_cnt[os];
    if (mo >= cnt) return;
    int mtile = min(MTILE, cnt - mo);

    int tid = threadIdx.x, wid = tid >> 5, lane = tid & 31;
    int gr = lane >> 2, tg = lane & 3;
    int s = os >> 7, o = os & 127, nbase = os * 32;

    ents[tid] = g_list[os * BATCH + mo + min(tid, mtile - 1)];
    if (tid < 32) madd[tid] = (s ? M2 : M1)[o * 32 + tid] + b2[nbase + tid];
    __syncthreads();

    const float* hrow = g_h + (size_t)(ents[tid] >> 5) * HID;

    float acc[2][4][4];
    #pragma unroll
    for (int t16 = 0; t16 < 2; t16++)
        #pragma unroll
        for (int nb = 0; nb < 4; nb++)
            #pragma unroll
            for (int i = 0; i < 4; i++) acc[t16][nb][i] = 0.0f;

    int mt = wid * 32;

    for (int kt = 0; kt < 16; kt++) {
        int k0 = kt * 32;
        __syncthreads();                  // protect previous iter's frag reads
        stage_row(ht2[tid], hrow + k0, tid);
        if (tid < 128) {                  // B tile: W2^T, coalesced across n
            int nn = tid & 31, ks = tid >> 5;
            const float* wp = W2 + (size_t)(k0 + ks * 8) * 8192 + nbase + nn;
            float v[8];
            #pragma unroll
            for (int t = 0; t < 8; t++)
                v[t] = __uint_as_float(f2tf32(wp[(size_t)t * 8192]));
            int key23 = (nn >> 1) & 3, key1 = nn & 1;
            float2* dst = &bt2[nn][(ks ^ key23) << 2];
            float4 p01 = make_float4(v[0], v[4], v[1], v[5]);
            float4 p23 = make_float4(v[2], v[6], v[3], v[7]);
            *(float4*)dst       = key1 ? p23 : p01;
            *(float4*)(dst + 2) = key1 ? p01 : p23;
        }
        __syncthreads();

        #pragma unroll
        for (int ks = 0; ks < 4; ks++) {
            float2 bf[4];
            #pragma unroll
            for (int nb = 0; nb < 4; nb++) {
                int nrow = nb * 8 + gr;
                bf[nb] = bt2[nrow][(ks * 4 + tg) ^ ((nrow & 7) << 1)];
            }
            #pragma unroll
            for (int t16 = 0; t16 < 2; t16++) {
                int r0 = mt + t16 * 16 + gr, r1 = r0 + 8;
                float2 a02 = ht2[r0][(ks * 4 + tg) ^ ((r0 & 7) << 1)];
                float2 a13 = ht2[r1][(ks * 4 + tg) ^ ((r1 & 7) << 1)];
                #pragma unroll
                for (int nb = 0; nb < 4; nb++)
                    mma_tf32(acc[t16][nb], fu(a02.x), fu(a13.x),
                             fu(a02.y), fu(a13.y), fu(bf[nb].x), fu(bf[nb].y));
            }
        }
    }

    // epilogue: + (M row + b2), scatter rows by (sample, slot)
    #pragma unroll
    for (int t16 = 0; t16 < 2; t16++) {
        int mmA = mt + t16 * 16 + gr, mmB = mmA + 8;
        int entA = ents[mmA], entB = ents[mmB];
        float* rowA = g_A + ((size_t)(s * BATCH + (entA >> 5)) * 32 + (entA & 31)) * 32;
        float* rowB = g_A + ((size_t)(s * BATCH + (entB >> 5)) * 32 + (entB & 31)) * 32;
        #pragma unroll
        for (int nb = 0; nb < 4; nb++) {
            int col = nb * 8 + 2 * tg;
            float mb0 = madd[col], mb1 = madd[col + 1];
            if (mmA < mtile)
                *(float2*)(rowA + col) = make_float2(acc[t16][nb][0] + mb0,
                                                     acc[t16][nb][1] + mb1);
            if (mmB < mtile)
                *(float2*)(rowB + col) = make_float2(acc[t16][nb][2] + mb0,
                                                     acc[t16][nb][3] + mb1);
        }
    }
}

// ---------------- K4: logdet via all-register warp LU (partial pivoting) ----
// one warp per sample; row-per-lane, matrix entirely in registers, zero smem.
__global__ void __launch_bounds__(256) k_det(float* __restrict__ out, int wide) {
    int gw   = (blockIdx.x * blockDim.x + threadIdx.x) >> 5;
    int lane = threadIdx.x & 31;

    float la = 0.0f;
    int nneg = 0;

    for (int s = 0; s < 2; s++) {
        float a[32];
        const float4* src = (const float4*)(g_A + (((size_t)(s * BATCH + gw)) << 10)
                                                + lane * 32);
        #pragma unroll
        for (int c4 = 0; c4 < 8; c4++) {
            float4 v = src[c4];
            a[c4 * 4 + 0] = v.x; a[c4 * 4 + 1] = v.y;
            a[c4 * 4 + 2] = v.z; a[c4 * 4 + 3] = v.w;
        }
        int neg = 0;
        #pragma unroll
        for (int k = 0; k < 32; k++) {
            float v = (lane >= k) ? fabsf(a[k]) : -1.0f;
            int idx = lane;
            #pragma unroll
            for (int off = 16; off > 0; off >>= 1) {
                float ov = __shfl_xor_sync(0xffffffffu, v,   off);
                int   oi = __shfl_xor_sync(0xffffffffu, idx, off);
                if (ov > v || (ov == v && oi < idx)) { v = ov; idx = oi; }
            }
            int p = idx;                                  // warp-uniform
            float tk = __shfl_sync(0xffffffffu, a[k], k);
            float tp = __shfl_sync(0xffffffffu, a[k], p);
            if (lane == p) a[k] = tk;
            if (lane == k) a[k] = tp;
            float piv = tp;
            neg ^= (piv < 0.0f) ? 1 : 0;
            neg ^= (p != k) ? 1 : 0;
            la += logf(fabsf(piv));
            float mult = a[k] / piv;                      // used only by lanes > k
            #pragma unroll
            for (int c = k + 1; c < 32; c++) {
                float tkc = __shfl_sync(0xffffffffu, a[c], k);
                float tpc = __shfl_sync(0xffffffffu, a[c], p);
                if (lane == p) a[c] = tkc;
                if (lane == k) a[c] = tpc;
                if (lane > k)  a[c] = fmaf(-mult, tpc, a[c]);
            }
        }
        nneg += neg;
    }
    if (lane == 0) {
        if (wide) {
            out[2 * gw]     = la;
            out[2 * gw + 1] = 3.14159274f * (float)nneg;
        } else {
            out[gw] = la;
        }
    }
}

// ---------------- launch (kernel launches ONLY — no host-side API calls) ----
extern "C" void kernel_launch(void* const* d_in, const int* in_sizes, int n_in,
                              void* d_out, int out_size) {
    const int*   n  = 0;
    const float *W1 = 0, *b1 = 0, *W2 = 0, *b2 = 0, *M1 = 0, *M2 = 0;
    for (int i = 0; i < n_in; i++) {
        switch (in_sizes[i]) {
            case 2097152: n  = (const int*)  d_in[i]; break;
            case 131072:  W1 = (const float*)d_in[i]; break;
            case 512:     b1 = (const float*)d_in[i]; break;
            case 4194304: W2 = (const float*)d_in[i]; break;
            case 8192:    b2 = (const float*)d_in[i]; break;
            case 4096:    if (!M1) M1 = (const float*)d_in[i];
                          else     M2 = (const float*)d_in[i];
                          break;
            default: break;
        }
    }

    int wide = (out_size >= 16384) ? 1 : 0;

    k_zero  <<<1, 256>>>();
    k_index <<<BATCH / 8, 256>>>(n);
    k_hidden<<<BATCH / 16, 512>>>(W1, b1);
    k_gemm  <<<dim3(NOS, YTILES), 256>>>(W2, b2, M1, M2);
    k_det   <<<BATCH / 8, 256>>>((float*)d_out, wide);
}

// round 11
// speedup vs baseline: 1.6035x; 1.6035x over previous
#include <cuda_runtime.h>
#include <cstdint>
#include <math.h>

#define BATCH 8192
#define NORB  128
#define NFER  32
#define HID   512
#define NOS   256          // orbital-sectors: 2 spin sectors * 128 orbitals
#define MTILE 256          // rows per k_gemm CTA (static smem, no attribute call)
#define YTILES 12          // covers bucket counts up to 3072 (mean 2048, sigma 39)

// ---------------- scratch (static device globals; no runtime allocation) ----
__device__ float    g_h[BATCH * HID];            // hidden activations (tf32-rounded)
__device__ unsigned g_mask[BATCH * 8];           // 256-bit occupancy bitmask per sample
__device__ int      g_cnt[NOS];                  // bucket counts
__device__ int      g_list[NOS * BATCH];         // bucket entries: (b<<5)|slot
__device__ float    g_A[2 * BATCH * NFER * NFER];// gathered backflow matrices

__device__ __forceinline__ unsigned f2tf32(float f) {
    unsigned u;
    asm("cvt.rna.tf32.f32 %0, %1;" : "=r"(u) : "f"(f));
    return u;
}
__device__ __forceinline__ unsigned fu(float f) { return __float_as_uint(f); }

__device__ __forceinline__ void mma_tf32(float c[4],
                                         unsigned a0, unsigned a1,
                                         unsigned a2, unsigned a3,
                                         unsigned b0, unsigned b1) {
    asm volatile(
        "mma.sync.aligned.m16n8k8.row.col.f32.tf32.tf32.f32 "
        "{%0,%1,%2,%3}, {%4,%5,%6,%7}, {%8,%9}, {%0,%1,%2,%3};"
        : "+f"(c[0]), "+f"(c[1]), "+f"(c[2]), "+f"(c[3])
        : "r"(a0), "r"(a1), "r"(a2), "r"(a3), "r"(b0), "r"(b1));
}

// ---------------- K0: zero bucket counters (must rerun every replay) --------
__global__ void k_zero() {
    if (threadIdx.x < NOS) g_cnt[threadIdx.x] = 0;
}

// ---------------- K1: occupancy scan, bitmasks, bucket build ----------------
__global__ void k_index(const int* __restrict__ n) {
    int gw   = (blockIdx.x * blockDim.x + threadIdx.x) >> 5;
    int lane = threadIdx.x & 31;
    int b    = gw;
    int cnt  = 0;
    #pragma unroll
    for (int c = 0; c < 8; c++) {
        if (c == 4) cnt = 0;             // sector boundary (k = 128)
        int v = n[b * 256 + c * 32 + lane];
        unsigned msk = __ballot_sync(0xffffffffu, v != 0);
        if (lane == 0) g_mask[b * 8 + c] = msk;
        int slot = cnt + __popc(msk & ((1u << lane) - 1u));
        cnt += __popc(msk);
        if (v) {
            int os  = ((c >> 2) << 7) | ((c & 3) << 5) | lane;
            int pos = atomicAdd(&g_cnt[os], 1);
            g_list[os * BATCH + pos] = (b << 5) | slot;
        }
    }
}

// ---------------- K2: h = tanh(b1 + sum of occupied W1 rows) ----------------
__global__ void __launch_bounds__(512) k_hidden(const float* __restrict__ W1,
                                                const float* __restrict__ b1) {
    __shared__ __align__(16) float tile[16 * 512];
    int tid  = threadIdx.x;
    int lane = tid & 31;
    int wsam = tid >> 5;
    int b    = blockIdx.x * 16 + wsam;

    float4 acc[4];
    #pragma unroll
    for (int i = 0; i < 4; i++) acc[i] = ((const float4*)b1)[i * 32 + lane];

    for (int t = 0; t < 16; t++) {
        int k0 = t * 16;
        __syncthreads();
        #pragma unroll
        for (int q = 0; q < 4; q++) {
            int ig = q * 512 + tid;
            ((float4*)tile)[ig] = ((const float4*)W1)[k0 * 128 + ig];
        }
        __syncthreads();
        unsigned bits = (g_mask[b * 8 + (t >> 1)] >> ((t & 1) * 16)) & 0xFFFFu;
        while (bits) {
            int kk = __ffs(bits) - 1; bits &= bits - 1;
            const float4* row = (const float4*)(tile + kk * 512);
            #pragma unroll
            for (int i = 0; i < 4; i++) {
                float4 v = row[i * 32 + lane];
                acc[i].x += v.x; acc[i].y += v.y; acc[i].z += v.z; acc[i].w += v.w;
            }
        }
    }
    float4* ho = (float4*)(g_h + b * HID);
    #pragma unroll
    for (int i = 0; i < 4; i++) {
        float4 v = acc[i];
        v.x = __uint_as_float(f2tf32(tanhf(v.x)));
        v.y = __uint_as_float(f2tf32(tanhf(v.y)));
        v.z = __uint_as_float(f2tf32(tanhf(v.z)));
        v.w = __uint_as_float(f2tf32(tanhf(v.w)));
        ho[i * 32 + lane] = v;
    }
}

// ---------------- K3: grouped masked GEMM (tf32 mma.sync, 256m tiles) -------
// Paired-float2 XOR-swizzled ht2 layout: logical 8B slot jl = ks*4+tg of row m
// stored at jp = jl ^ ((m&7)<<1); fragment pairs (a0,a2)/(a1,a3)/(b0,b1) are
// single conflict-minimal LDS.64.
// A-gather is ROW-COOPERATIVE: 8 threads load one row's 128B (warp = 4 rows
// = 4 L1 lines = 1 wavefront/row, 8x fewer than row-per-thread), then a
// shfl_xor(1) partner exchange builds the (v[j], v[j+4]) pairs for one
// swizzled STS.128 per thread.
__global__ void __launch_bounds__(256)
k_gemm(const float* __restrict__ W2, const float* __restrict__ b2,
       const float* __restrict__ M1, const float* __restrict__ M2) {
    __shared__ __align__(16) float2 ht2[MTILE][16];   // 32 KB
    __shared__ __align__(16) float2 bt2[32][16];      //  4 KB
    __shared__ int   ents[MTILE];
    __shared__ float madd[32];

    int os = blockIdx.x;
    int mo = blockIdx.y * MTILE;
    int cnt = g_cnt[os];
    if (mo >= cnt) return;
    int mtile = min(MTILE, cnt - mo);

    int tid = threadIdx.x, wid = tid >> 5, lane = tid & 31;
    int gr = lane >> 2, tg = lane & 3;
    int s = os >> 7, o = os & 127, nbase = os * 32;

    ents[tid] = g_list[os * BATCH + mo + min(tid, mtile - 1)];
    if (tid < 32) madd[tid] = (s ? M2 : M1)[o * 32 + tid] + b2[nbase + tid];
    __syncthreads();

    // gather assignment: 8 threads per row; rows rb, rb+32, ..., rb+224
    int rb = tid >> 3;                   // row base 0..31
    int ch = tid & 7;                    // 16B chunk 0..7 within 128B
    int half = ch & 1;                   // 0: va (k j..j+3), 1: vb (k j+4..j+7)
    int ksg = ch >> 1;                   // ks group of this chunk pair
    int key1 = rb & 1;                   // row&1  (p*32 keeps parity)
    int key23 = (rb >> 1) & 3;           // (row>>1)&3 (p*16 = 0 mod 4)
    unsigned hoff[8];
    #pragma unroll
    for (int p = 0; p < 8; p++)
        hoff[p] = (unsigned)(ents[p * 32 + rb] >> 5) * HID;

    float acc[2][4][4];
    #pragma unroll
    for (int t16 = 0; t16 < 2; t16++)
        #pragma unroll
        for (int nb = 0; nb < 4; nb++)
            #pragma unroll
            for (int i = 0; i < 4; i++) acc[t16][nb][i] = 0.0f;

    int mt = wid * 32;

    for (int kt = 0; kt < 16; kt++) {
        int k0 = kt * 32;
        __syncthreads();                  // protect previous iter's frag reads
        // ---- stage A: row-cooperative coalesced gather + partner exchange
        #pragma unroll
        for (int p = 0; p < 8; p++) {
            int row = p * 32 + rb;
            float4 f4 = *(const float4*)(g_h + (size_t)hoff[p] + k0 + ch * 4);
            float4 of4;
            of4.x = __shfl_xor_sync(0xffffffffu, f4.x, 1);
            of4.y = __shfl_xor_sync(0xffffffffu, f4.y, 1);
            of4.z = __shfl_xor_sync(0xffffffffu, f4.z, 1);
            of4.w = __shfl_xor_sync(0xffffffffu, f4.w, 1);
            float4 va = half ? of4 : f4;
            float4 vb = half ? f4 : of4;
            float4 p01 = make_float4(va.x, vb.x, va.y, vb.y);
            float4 p23 = make_float4(va.z, vb.z, va.w, vb.w);
            float4 val = (half ^ key1) ? p23 : p01;
            *(float4*)(&ht2[row][((ksg ^ key23) << 2) + half * 2]) = val;
        }
        // ---- stage B tile: W2^T, coalesced across n
        if (tid < 128) {
            int nn = tid & 31, ks = tid >> 5;
            const float* wp = W2 + (size_t)(k0 + ks * 8) * 8192 + nbase + nn;
            float v[8];
            #pragma unroll
            for (int t = 0; t < 8; t++)
                v[t] = __uint_as_float(f2tf32(wp[(size_t)t * 8192]));
            int bk23 = (nn >> 1) & 3, bk1 = nn & 1;
            float2* dst = &bt2[nn][(ks ^ bk23) << 2];
            float4 p01 = make_float4(v[0], v[4], v[1], v[5]);
            float4 p23 = make_float4(v[2], v[6], v[3], v[7]);
            *(float4*)dst       = bk1 ? p23 : p01;
            *(float4*)(dst + 2) = bk1 ? p01 : p23;
        }
        __syncthreads();

        #pragma unroll
        for (int ks = 0; ks < 4; ks++) {
            float2 bf[4];
            #pragma unroll
            for (int nb = 0; nb < 4; nb++) {
                int nrow = nb * 8 + gr;
                bf[nb] = bt2[nrow][(ks * 4 + tg) ^ ((nrow & 7) << 1)];
            }
            #pragma unroll
            for (int t16 = 0; t16 < 2; t16++) {
                int r0 = mt + t16 * 16 + gr, r1 = r0 + 8;
                float2 a02 = ht2[r0][(ks * 4 + tg) ^ ((r0 & 7) << 1)];
                float2 a13 = ht2[r1][(ks * 4 + tg) ^ ((r1 & 7) << 1)];
                #pragma unroll
                for (int nb = 0; nb < 4; nb++)
                    mma_tf32(acc[t16][nb], fu(a02.x), fu(a13.x),
                             fu(a02.y), fu(a13.y), fu(bf[nb].x), fu(bf[nb].y));
            }
        }
    }

    // epilogue: + (M row + b2), scatter rows by (sample, slot)
    #pragma unroll
    for (int t16 = 0; t16 < 2; t16++) {
        int mmA = mt + t16 * 16 + gr, mmB = mmA + 8;
        int entA = ents[mmA], entB = ents[mmB];
        float* rowA = g_A + ((size_t)(s * BATCH + (entA >> 5)) * 32 + (entA & 31)) * 32;
        float* rowB = g_A + ((size_t)(s * BATCH + (entB >> 5)) * 32 + (entB & 31)) * 32;
        #pragma unroll
        for (int nb = 0; nb < 4; nb++) {
            int col = nb * 8 + 2 * tg;
            float mb0 = madd[col], mb1 = madd[col + 1];
            if (mmA < mtile)
                *(float2*)(rowA + col) = make_float2(acc[t16][nb][0] + mb0,
                                                     acc[t16][nb][1] + mb1);
            if (mmB < mtile)
                *(float2*)(rowB + col) = make_float2(acc[t16][nb][2] + mb0,
                                                     acc[t16][nb][3] + mb1);
        }
    }
}

// ---------------- K4: logdet via warp LU (smem, partial pivoting) -----------
// round-5 version (compact rolled loops; register-LU variant I-cache-thrashed)
__global__ void __launch_bounds__(256) k_det(float* __restrict__ out, int wide) {
    __shared__ float As[8][32][33];
    int w    = threadIdx.x >> 5;
    int lane = threadIdx.x & 31;
    int b    = blockIdx.x * 8 + w;

    float la = 0.0f;
    int nneg = 0;

    for (int s = 0; s < 2; s++) {
        float (*A)[33] = As[w];
        const float* src = g_A + (((size_t)(s * BATCH + b)) << 10);
        #pragma unroll
        for (int r = 0; r < 32; r++) A[r][lane] = src[r * 32 + lane];
        __syncwarp();

        int neg = 0;
        for (int k = 0; k < 32; k++) {
            float v = (lane >= k) ? fabsf(A[lane][k]) : -1.0f;
            int idx = lane;
            #pragma unroll
            for (int off = 16; off > 0; off >>= 1) {
                float ov = __shfl_xor_sync(0xffffffffu, v,   off);
                int   oi = __shfl_xor_sync(0xffffffffu, idx, off);
                if (ov > v || (ov == v && oi < idx)) { v = ov; idx = oi; }
            }
            int p = idx;                 // warp-uniform
            if (p != k) {                // swap rows k<->p (lane = column)
                float t = A[k][lane];
                A[k][lane] = A[p][lane];
                A[p][lane] = t;
                neg ^= 1;
            }
            __syncwarp();

            float piv = A[k][k];
            neg ^= (piv < 0.0f) ? 1 : 0;
            la += logf(fabsf(piv));
            float inv = 1.0f / piv;
            float prow = A[k][lane];
            float mcol = A[lane][k];
            __syncwarp();
            for (int r = k + 1; r < 32; r++) {
                float mult = __shfl_sync(0xffffffffu, mcol, r) * inv;
                A[r][lane] = fmaf(-mult, prow, A[r][lane]);
            }
            __syncwarp();
        }
        nneg += neg;
    }
    if (lane == 0) {
        if (wide) {
            out[2 * b]     = la;
            out[2 * b + 1] = 3.14159274f * (float)nneg;
        } else {
            out[b] = la;
        }
    }
}

// ---------------- launch (kernel launches ONLY — no host-side API calls) ----
extern "C" void kernel_launch(void* const* d_in, const int* in_sizes, int n_in,
                              void* d_out, int out_size) {
    const int*   n  = 0;
    const float *W1 = 0, *b1 = 0, *W2 = 0, *b2 = 0, *M1 = 0, *M2 = 0;
    for (int i = 0; i < n_in; i++) {
        switch (in_sizes[i]) {
            case 2097152: n  = (const int*)  d_in[i]; break;
            case 131072:  W1 = (const float*)d_in[i]; break;
            case 512:     b1 = (const float*)d_in[i]; break;
            case 4194304: W2 = (const float*)d_in[i]; break;
            case 8192:    b2 = (const float*)d_in[i]; break;
            case 4096:    if (!M1) M1 = (const float*)d_in[i];
                          else     M2 = (const float*)d_in[i];
                          break;
            default: break;
        }
    }

    int wide = (out_size >= 16384) ? 1 : 0;

    k_zero  <<<1, 256>>>();
    k_index <<<BATCH / 8, 256>>>(n);
    k_hidden<<<BATCH / 16, 512>>>(W1, b1);
    k_gemm  <<<dim3(NOS, YTILES), 256>>>(W2, b2, M1, M2);
    k_det   <<<BATCH / 8, 256>>>((float*)d_out, wide);
}